// round 15
// baseline (speedup 1.0000x reference)
#include <cuda_runtime.h>

#define TT 512
#define CC 256
#define LL 128
#define SS 257          // 2L+1
#define NWARP 9
#define NTH 288
#define PAD 8
#define EPSF 1e-7f
#define LN2F 0.69314718055994530942f
#define FULLM 0xffffffffu

struct alignas(16) Smem {
    float P[2][3][4 * CC];    // [batch][buf][4 rows]; float4-accessed
    float A[2][2][PAD + SS];  // [batch][pingpong], front-padded zeros
    float wmax[2][2][NWARP];  // [batch][pingpong]
    int   ecls[2][SS];
    float eskip[2][SS];
};

// Advance K steps for BOTH batches with ONE barrier. Thread s recomputes the
// cone alpha[s-2K..s] -> alpha_new[s]. Every cell is uniform:
//   v[d] = (v[d+1]+v[d+2] + skpA[off]*v[d]) * P[clsA[off]]
// (blank / out-of-range offsets carry class=blank, skip=0).
// scl applied to cone INPUTS (FTZ-safe); 2-deep LDG->reg->STS prefetch.
template<int K>
__device__ __forceinline__ void step2(
    Smem& sm, int src, int dst, int pbuf, int roff,
    const int clsA[2][8], const float skpA[2][8],
    int s, int tid, int esum[2],
    const float4 hold[2], bool doSts, int stsBuf,
    const float* ldg0, const float* ldg1, float4 fresh[2])
{
    // prefetch LDGs first (consumed 2 iterations later)
    const bool doLdg = (ldg0 != nullptr) && (tid < 256);
    if (doLdg) {
        fresh[0] = reinterpret_cast<const float4*>(ldg0)[tid];
        fresh[1] = reinterpret_cast<const float4*>(ldg1)[tid];
    }

    // per-batch block max -> exact power-of-two rescale
    float scl[2];
    #pragma unroll
    for (int q = 0; q < 2; ++q) {
        float m = sm.wmax[q][src][0];
        #pragma unroll
        for (int w = 1; w < NWARP; ++w) m = fmaxf(m, sm.wmax[q][src][w]);
        const int e = (int)(__float_as_uint(m) >> 23) - 127;
        esum[q] += e;
        scl[q] = __uint_as_float((unsigned)(127 - e) << 23);
    }

    const bool act = (tid < SS);

    float v[2][2 * K + 1];
    #pragma unroll
    for (int q = 0; q < 2; ++q)
        #pragma unroll
        for (int d = 0; d <= 2 * K; ++d)
            v[q][d] = act ? sm.A[q][src][s + d + (PAD - 2 * K)] * scl[q] : 0.f;

    #pragma unroll
    for (int r = 0; r < K; ++r) {
        const float* P0 = &sm.P[0][pbuf][(roff + r) * CC];
        const float* P1 = &sm.P[1][pbuf][(roff + r) * CC];
        const int w = 2 * (K - 1 - r) + 1;
        #pragma unroll
        for (int d = 0; d < w; ++d) {
            const int off = (w - 1) - d;
            {
                const float sum2 = v[0][d + 1] + v[0][d + 2];
                const float t = fmaf(skpA[0][off], v[0][d], sum2);
                v[0][d] = t * P0[clsA[0][off]];
            }
            {
                const float sum2 = v[1][d + 1] + v[1][d + 2];
                const float t = fmaf(skpA[1][off], v[1][d], sum2);
                v[1][d] = t * P1[clsA[1][off]];
            }
        }
    }

    #pragma unroll
    for (int q = 0; q < 2; ++q) {
        const float fin = act ? v[q][0] : 0.f;
        const unsigned wm = __reduce_max_sync(FULLM, __float_as_uint(fin));
        if (act) sm.A[q][dst][PAD + s] = fin;
        if ((tid & 31) == 0) sm.wmax[q][dst][tid >> 5] = __uint_as_float(wm);
    }

    // stage the group held in registers (loaded last iteration)
    if (doSts && tid < 256) {
        #pragma unroll
        for (int q = 0; q < 2; ++q) {
            float4 a = hold[q];
            a.x += EPSF; a.y += EPSF; a.z += EPSF; a.w += EPSF;
            reinterpret_cast<float4*>(&sm.P[q][stsBuf][0])[tid] = a;
        }
    }
    __syncthreads();
}

__global__ __launch_bounds__(NTH, 1)
void ctc_dual(const int* __restrict__ y_true,
              const float* __restrict__ y_pred,
              float* __restrict__ out)
{
    __shared__ Smem sm;
    const int c = blockIdx.x;           // handles batches 2c, 2c+1
    const int tid = threadIdx.x;
    const int s = tid;
    const bool act = (tid < SS);

    const float* base[2] = { y_pred + (size_t)(2 * c) * TT * CC,
                             y_pred + (size_t)(2 * c + 1) * TT * CC };

    // ---- setup: extended labels, skip flags, pads ----
    #pragma unroll
    for (int q = 0; q < 2; ++q) {
        if (act) {
            int cl = CC - 1; float sk = 0.f;
            if (tid & 1) {
                const int j = tid >> 1;
                cl = y_true[(2 * c + q) * LL + j];
                sk = (j >= 1 && cl != y_true[(2 * c + q) * LL + j - 1]) ? 1.f : 0.f;
            }
            sm.ecls[q][tid] = cl;
            sm.eskip[q][tid] = sk;
        }
        if (tid < PAD) { sm.A[q][0][tid] = 0.f; sm.A[q][1][tid] = 0.f; }
    }

    // stage groups 0 and 1 (rows 0..7) for both batches; preload group 2
    float4 hold[2], fresh[2];
    if (tid < 256) {
        #pragma unroll
        for (int q = 0; q < 2; ++q) {
            #pragma unroll
            for (int g = 0; g < 2; ++g) {
                float4 v = reinterpret_cast<const float4*>(base[q] + g * 4 * CC)[tid];
                v.x += EPSF; v.y += EPSF; v.z += EPSF; v.w += EPSF;
                reinterpret_cast<float4*>(&sm.P[q][g][0])[tid] = v;
            }
            hold[q] = reinterpret_cast<const float4*>(base[q] + 2 * 4 * CC)[tid];
        }
    }
    __syncthreads();

    // per-thread class/skip for ALL offsets 0..7 (uniform cells)
    int clsA[2][8]; float skpA[2][8];
    #pragma unroll
    for (int q = 0; q < 2; ++q)
        #pragma unroll
        for (int o = 0; o < 8; ++o) {
            const int pos = s - o;
            const bool lab = act && (pos >= 1) && (pos & 1);
            clsA[q][o] = lab ? sm.ecls[q][pos] : (CC - 1);
            skpA[q][o] = lab ? sm.eskip[q][pos] : 0.f;
        }

    // ---- alpha0 ----
    #pragma unroll
    for (int q = 0; q < 2; ++q) {
        float v0 = 0.f;
        if (act) {
            v0 = (tid < 2) ? sm.P[q][0][sm.ecls[q][tid]] : 0.f;
            sm.A[q][0][PAD + tid] = v0;
        }
        const unsigned wm = __reduce_max_sync(FULLM, __float_as_uint(v0));
        if ((tid & 31) == 0) sm.wmax[q][0][tid >> 5] = __uint_as_float(wm);
    }
    __syncthreads();

    int esum[2] = {0, 0};

    // iter 0: K=3 (t=1..3 = group 0 rows 1..3); LDG group 3; STS group 2 -> buf 2
    step2<3>(sm, 0, 1, 0, 1, clsA, skpA, s, tid, esum,
             hold, true, 2,
             base[0] + (size_t)3 * 4 * CC, base[1] + (size_t)3 * 4 * CC, fresh);
    hold[0] = fresh[0]; hold[1] = fresh[1];

    // iters 1..127: K=4 on group i (t = 4i..4i+3)
    for (int i = 1; i < 128; ++i) {
        const int src = i & 1;
        const int dst = 1 - src;
        const float* l0 = nullptr; const float* l1 = nullptr;
        if (i <= 124) {
            l0 = base[0] + (size_t)(i + 3) * 4 * CC;
            l1 = base[1] + (size_t)(i + 3) * 4 * CC;
        }
        const bool doSts = (i <= 125);
        step2<4>(sm, src, dst, i % 3, 0, clsA, skpA, s, tid, esum,
                 hold, doSts, (i + 2) % 3, l0, l1, fresh);
        hold[0] = fresh[0]; hold[1] = fresh[1];
    }

    if (tid == 0) {
        // last iter i=127: dst = 0
        #pragma unroll
        for (int q = 0; q < 2; ++q) {
            const float s2 = sm.A[q][0][PAD + SS - 1] + sm.A[q][0][PAD + SS - 2];
            out[2 * c + q] = -(logf(s2) + LN2F * (float)esum[q]);
        }
    }
}

extern "C" void kernel_launch(void* const* d_in, const int* in_sizes, int n_in,
                              void* d_out, int out_size)
{
    const int* yt;
    const float* yp;
    if (in_sizes[0] < in_sizes[1]) {
        yt = (const int*)d_in[0];
        yp = (const float*)d_in[1];
    } else {
        yt = (const int*)d_in[1];
        yp = (const float*)d_in[0];
    }
    ctc_dual<<<128, NTH>>>(yt, yp, (float*)d_out);
}

// round 16
// speedup vs baseline: 1.0029x; 1.0029x over previous
#include <cuda_runtime.h>

#define TT 512
#define CC 256
#define LL 128
#define SS 257          // 2L+1
#define NWARP 9
#define NTH 288
#define PAD 8
#define EPSF 1e-7f
#define LN2F 0.69314718055994530942f
#define FULLM 0xffffffffu

struct alignas(16) Smem {
    float P[2][3][4 * CC];    // [batch][buf][4 rows]; float4-accessed
    float A[2][2][PAD + SS];  // [batch][pingpong], front-padded zeros
    float wmax[2][2][NWARP];  // [batch][pingpong]
    int   ecls[2][SS];
    float eskip[2][SS];
};

// Advance K steps for BOTH batches with ONE barrier. Thread s recomputes the
// cone alpha[s-2K..s] -> alpha_new[s]. Every cell is uniform:
//   v[d] = (v[d+1]+v[d+2] + skpA[off]*v[d]) * P[clsA[off]]
// (blank / out-of-range offsets carry class=blank, skip=0).
// scl applied to cone INPUTS (FTZ-safe); 2-deep LDG->reg->STS prefetch.
template<int K>
__device__ __forceinline__ void step2(
    Smem& sm, int src, int dst, int pbuf, int roff,
    const int clsA[2][8], const float skpA[2][8],
    int s, int tid, int esum[2],
    const float4 hold[2], bool doSts, int stsBuf,
    const float* ldg0, const float* ldg1, float4 fresh[2])
{
    // prefetch LDGs first (consumed 2 iterations later)
    const bool doLdg = (ldg0 != nullptr) && (tid < 256);
    if (doLdg) {
        fresh[0] = reinterpret_cast<const float4*>(ldg0)[tid];
        fresh[1] = reinterpret_cast<const float4*>(ldg1)[tid];
    }

    // per-batch block max -> exact power-of-two rescale
    float scl[2];
    #pragma unroll
    for (int q = 0; q < 2; ++q) {
        float m = sm.wmax[q][src][0];
        #pragma unroll
        for (int w = 1; w < NWARP; ++w) m = fmaxf(m, sm.wmax[q][src][w]);
        const int e = (int)(__float_as_uint(m) >> 23) - 127;
        esum[q] += e;
        scl[q] = __uint_as_float((unsigned)(127 - e) << 23);
    }

    const bool act = (tid < SS);

    float v[2][2 * K + 1];
    #pragma unroll
    for (int q = 0; q < 2; ++q)
        #pragma unroll
        for (int d = 0; d <= 2 * K; ++d)
            v[q][d] = act ? sm.A[q][src][s + d + (PAD - 2 * K)] * scl[q] : 0.f;

    #pragma unroll
    for (int r = 0; r < K; ++r) {
        const float* P0 = &sm.P[0][pbuf][(roff + r) * CC];
        const float* P1 = &sm.P[1][pbuf][(roff + r) * CC];
        const int w = 2 * (K - 1 - r) + 1;
        #pragma unroll
        for (int d = 0; d < w; ++d) {
            const int off = (w - 1) - d;
            {
                const float sum2 = v[0][d + 1] + v[0][d + 2];
                const float t = fmaf(skpA[0][off], v[0][d], sum2);
                v[0][d] = t * P0[clsA[0][off]];
            }
            {
                const float sum2 = v[1][d + 1] + v[1][d + 2];
                const float t = fmaf(skpA[1][off], v[1][d], sum2);
                v[1][d] = t * P1[clsA[1][off]];
            }
        }
    }

    #pragma unroll
    for (int q = 0; q < 2; ++q) {
        const float fin = act ? v[q][0] : 0.f;
        const unsigned wm = __reduce_max_sync(FULLM, __float_as_uint(fin));
        if (act) sm.A[q][dst][PAD + s] = fin;
        if ((tid & 31) == 0) sm.wmax[q][dst][tid >> 5] = __uint_as_float(wm);
    }

    // stage the group held in registers (loaded last iteration)
    if (doSts && tid < 256) {
        #pragma unroll
        for (int q = 0; q < 2; ++q) {
            float4 a = hold[q];
            a.x += EPSF; a.y += EPSF; a.z += EPSF; a.w += EPSF;
            reinterpret_cast<float4*>(&sm.P[q][stsBuf][0])[tid] = a;
        }
    }
    __syncthreads();
}

__global__ __launch_bounds__(NTH, 1)
void ctc_dual(const int* __restrict__ y_true,
              const float* __restrict__ y_pred,
              float* __restrict__ out)
{
    __shared__ Smem sm;
    const int c = blockIdx.x;           // handles batches 2c, 2c+1
    const int tid = threadIdx.x;
    const int s = tid;
    const bool act = (tid < SS);

    const float* base[2] = { y_pred + (size_t)(2 * c) * TT * CC,
                             y_pred + (size_t)(2 * c + 1) * TT * CC };

    // ---- setup: extended labels, skip flags, pads ----
    #pragma unroll
    for (int q = 0; q < 2; ++q) {
        if (act) {
            int cl = CC - 1; float sk = 0.f;
            if (tid & 1) {
                const int j = tid >> 1;
                cl = y_true[(2 * c + q) * LL + j];
                sk = (j >= 1 && cl != y_true[(2 * c + q) * LL + j - 1]) ? 1.f : 0.f;
            }
            sm.ecls[q][tid] = cl;
            sm.eskip[q][tid] = sk;
        }
        if (tid < PAD) { sm.A[q][0][tid] = 0.f; sm.A[q][1][tid] = 0.f; }
    }

    // stage groups 0 and 1 (rows 0..7) for both batches; preload group 2
    float4 hold[2], fresh[2];
    if (tid < 256) {
        #pragma unroll
        for (int q = 0; q < 2; ++q) {
            #pragma unroll
            for (int g = 0; g < 2; ++g) {
                float4 v = reinterpret_cast<const float4*>(base[q] + g * 4 * CC)[tid];
                v.x += EPSF; v.y += EPSF; v.z += EPSF; v.w += EPSF;
                reinterpret_cast<float4*>(&sm.P[q][g][0])[tid] = v;
            }
            hold[q] = reinterpret_cast<const float4*>(base[q] + 2 * 4 * CC)[tid];
        }
    }
    __syncthreads();

    // per-thread class/skip for ALL offsets 0..7 (uniform cells)
    int clsA[2][8]; float skpA[2][8];
    #pragma unroll
    for (int q = 0; q < 2; ++q)
        #pragma unroll
        for (int o = 0; o < 8; ++o) {
            const int pos = s - o;
            const bool lab = act && (pos >= 1) && (pos & 1);
            clsA[q][o] = lab ? sm.ecls[q][pos] : (CC - 1);
            skpA[q][o] = lab ? sm.eskip[q][pos] : 0.f;
        }

    // ---- alpha0 ----
    #pragma unroll
    for (int q = 0; q < 2; ++q) {
        float v0 = 0.f;
        if (act) {
            v0 = (tid < 2) ? sm.P[q][0][sm.ecls[q][tid]] : 0.f;
            sm.A[q][0][PAD + tid] = v0;
        }
        const unsigned wm = __reduce_max_sync(FULLM, __float_as_uint(v0));
        if ((tid & 31) == 0) sm.wmax[q][0][tid >> 5] = __uint_as_float(wm);
    }
    __syncthreads();

    int esum[2] = {0, 0};

    // iter 0: K=3 (t=1..3 = group 0 rows 1..3); LDG group 3; STS group 2 -> buf 2
    step2<3>(sm, 0, 1, 0, 1, clsA, skpA, s, tid, esum,
             hold, true, 2,
             base[0] + (size_t)3 * 4 * CC, base[1] + (size_t)3 * 4 * CC, fresh);
    hold[0] = fresh[0]; hold[1] = fresh[1];

    // iters 1..127: K=4 on group i (t = 4i..4i+3)
    for (int i = 1; i < 128; ++i) {
        const int src = i & 1;
        const int dst = 1 - src;
        const float* l0 = nullptr; const float* l1 = nullptr;
        if (i <= 124) {
            l0 = base[0] + (size_t)(i + 3) * 4 * CC;
            l1 = base[1] + (size_t)(i + 3) * 4 * CC;
        }
        const bool doSts = (i <= 125);
        step2<4>(sm, src, dst, i % 3, 0, clsA, skpA, s, tid, esum,
                 hold, doSts, (i + 2) % 3, l0, l1, fresh);
        hold[0] = fresh[0]; hold[1] = fresh[1];
    }

    if (tid == 0) {
        // last iter i=127: dst = 0
        #pragma unroll
        for (int q = 0; q < 2; ++q) {
            const float s2 = sm.A[q][0][PAD + SS - 1] + sm.A[q][0][PAD + SS - 2];
            out[2 * c + q] = -(logf(s2) + LN2F * (float)esum[q]);
        }
    }
}

extern "C" void kernel_launch(void* const* d_in, const int* in_sizes, int n_in,
                              void* d_out, int out_size)
{
    const int* yt;
    const float* yp;
    if (in_sizes[0] < in_sizes[1]) {
        yt = (const int*)d_in[0];
        yp = (const float*)d_in[1];
    } else {
        yt = (const int*)d_in[1];
        yp = (const float*)d_in[0];
    }
    ctc_dual<<<128, NTH>>>(yt, yp, (float*)d_out);
}

// round 17
// speedup vs baseline: 1.0032x; 1.0003x over previous
#include <cuda_runtime.h>

#define TT 512
#define CC 256
#define LL 128
#define SS 257          // 2L+1
#define NWARP 9
#define NTH 288
#define PAD 8
#define EPSF 1e-7f
#define LN2F 0.69314718055994530942f
#define FULLM 0xffffffffu

struct alignas(16) Smem {
    float P[2][3][4 * CC];    // [batch][buf][4 rows]; float4-accessed
    float A[2][2][PAD + SS];  // [batch][pingpong], front-padded zeros
    float wmax[2][2][NWARP];  // [batch][pingpong]
    int   ecls[2][SS];
    float eskip[2][SS];
};

// Advance K steps for BOTH batches with ONE barrier. Thread s recomputes the
// cone alpha[s-2K..s] -> alpha_new[s]. Every cell is uniform:
//   v[d] = (v[d+1]+v[d+2] + skpA[off]*v[d]) * P[clsA[off]]
// (blank / out-of-range offsets carry class=blank, skip=0).
// scl applied to cone INPUTS (FTZ-safe); 2-deep LDG->reg->STS prefetch.
template<int K>
__device__ __forceinline__ void step2(
    Smem& sm, int src, int dst, int pbuf, int roff,
    const int clsA[2][8], const float skpA[2][8],
    int s, int tid, int esum[2],
    const float4 hold[2], bool doSts, int stsBuf,
    const float* ldg0, const float* ldg1, float4 fresh[2])
{
    // prefetch LDGs first (consumed 2 iterations later)
    const bool doLdg = (ldg0 != nullptr) && (tid < 256);
    if (doLdg) {
        fresh[0] = reinterpret_cast<const float4*>(ldg0)[tid];
        fresh[1] = reinterpret_cast<const float4*>(ldg1)[tid];
    }

    // per-batch block max -> exact power-of-two rescale
    float scl[2];
    #pragma unroll
    for (int q = 0; q < 2; ++q) {
        float m = sm.wmax[q][src][0];
        #pragma unroll
        for (int w = 1; w < NWARP; ++w) m = fmaxf(m, sm.wmax[q][src][w]);
        const int e = (int)(__float_as_uint(m) >> 23) - 127;
        esum[q] += e;
        scl[q] = __uint_as_float((unsigned)(127 - e) << 23);
    }

    const bool act = (tid < SS);

    float v[2][2 * K + 1];
    #pragma unroll
    for (int q = 0; q < 2; ++q)
        #pragma unroll
        for (int d = 0; d <= 2 * K; ++d)
            v[q][d] = act ? sm.A[q][src][s + d + (PAD - 2 * K)] * scl[q] : 0.f;

    #pragma unroll
    for (int r = 0; r < K; ++r) {
        const float* P0 = &sm.P[0][pbuf][(roff + r) * CC];
        const float* P1 = &sm.P[1][pbuf][(roff + r) * CC];
        const int w = 2 * (K - 1 - r) + 1;
        #pragma unroll
        for (int d = 0; d < w; ++d) {
            const int off = (w - 1) - d;
            {
                const float sum2 = v[0][d + 1] + v[0][d + 2];
                const float t = fmaf(skpA[0][off], v[0][d], sum2);
                v[0][d] = t * P0[clsA[0][off]];
            }
            {
                const float sum2 = v[1][d + 1] + v[1][d + 2];
                const float t = fmaf(skpA[1][off], v[1][d], sum2);
                v[1][d] = t * P1[clsA[1][off]];
            }
        }
    }

    #pragma unroll
    for (int q = 0; q < 2; ++q) {
        const float fin = act ? v[q][0] : 0.f;
        const unsigned wm = __reduce_max_sync(FULLM, __float_as_uint(fin));
        if (act) sm.A[q][dst][PAD + s] = fin;
        if ((tid & 31) == 0) sm.wmax[q][dst][tid >> 5] = __uint_as_float(wm);
    }

    // stage the group held in registers (loaded last iteration)
    if (doSts && tid < 256) {
        #pragma unroll
        for (int q = 0; q < 2; ++q) {
            float4 a = hold[q];
            a.x += EPSF; a.y += EPSF; a.z += EPSF; a.w += EPSF;
            reinterpret_cast<float4*>(&sm.P[q][stsBuf][0])[tid] = a;
        }
    }
    __syncthreads();
}

__global__ __launch_bounds__(NTH, 1)
void ctc_dual(const int* __restrict__ y_true,
              const float* __restrict__ y_pred,
              float* __restrict__ out)
{
    __shared__ Smem sm;
    const int c = blockIdx.x;           // handles batches 2c, 2c+1
    const int tid = threadIdx.x;
    const int s = tid;
    const bool act = (tid < SS);

    const float* base[2] = { y_pred + (size_t)(2 * c) * TT * CC,
                             y_pred + (size_t)(2 * c + 1) * TT * CC };

    // ---- setup: extended labels, skip flags, pads ----
    #pragma unroll
    for (int q = 0; q < 2; ++q) {
        if (act) {
            int cl = CC - 1; float sk = 0.f;
            if (tid & 1) {
                const int j = tid >> 1;
                cl = y_true[(2 * c + q) * LL + j];
                sk = (j >= 1 && cl != y_true[(2 * c + q) * LL + j - 1]) ? 1.f : 0.f;
            }
            sm.ecls[q][tid] = cl;
            sm.eskip[q][tid] = sk;
        }
        if (tid < PAD) { sm.A[q][0][tid] = 0.f; sm.A[q][1][tid] = 0.f; }
    }

    // stage groups 0 and 1 (rows 0..7) for both batches; preload group 2
    float4 hold[2], fresh[2];
    if (tid < 256) {
        #pragma unroll
        for (int q = 0; q < 2; ++q) {
            #pragma unroll
            for (int g = 0; g < 2; ++g) {
                float4 v = reinterpret_cast<const float4*>(base[q] + g * 4 * CC)[tid];
                v.x += EPSF; v.y += EPSF; v.z += EPSF; v.w += EPSF;
                reinterpret_cast<float4*>(&sm.P[q][g][0])[tid] = v;
            }
            hold[q] = reinterpret_cast<const float4*>(base[q] + 2 * 4 * CC)[tid];
        }
    }
    __syncthreads();

    // per-thread class/skip for ALL offsets 0..7 (uniform cells)
    int clsA[2][8]; float skpA[2][8];
    #pragma unroll
    for (int q = 0; q < 2; ++q)
        #pragma unroll
        for (int o = 0; o < 8; ++o) {
            const int pos = s - o;
            const bool lab = act && (pos >= 1) && (pos & 1);
            clsA[q][o] = lab ? sm.ecls[q][pos] : (CC - 1);
            skpA[q][o] = lab ? sm.eskip[q][pos] : 0.f;
        }

    // ---- alpha0 ----
    #pragma unroll
    for (int q = 0; q < 2; ++q) {
        float v0 = 0.f;
        if (act) {
            v0 = (tid < 2) ? sm.P[q][0][sm.ecls[q][tid]] : 0.f;
            sm.A[q][0][PAD + tid] = v0;
        }
        const unsigned wm = __reduce_max_sync(FULLM, __float_as_uint(v0));
        if ((tid & 31) == 0) sm.wmax[q][0][tid >> 5] = __uint_as_float(wm);
    }
    __syncthreads();

    int esum[2] = {0, 0};

    // iter 0: K=3 (t=1..3 = group 0 rows 1..3); LDG group 3; STS group 2 -> buf 2
    step2<3>(sm, 0, 1, 0, 1, clsA, skpA, s, tid, esum,
             hold, true, 2,
             base[0] + (size_t)3 * 4 * CC, base[1] + (size_t)3 * 4 * CC, fresh);
    hold[0] = fresh[0]; hold[1] = fresh[1];

    // iters 1..127: K=4 on group i (t = 4i..4i+3)
    for (int i = 1; i < 128; ++i) {
        const int src = i & 1;
        const int dst = 1 - src;
        const float* l0 = nullptr; const float* l1 = nullptr;
        if (i <= 124) {
            l0 = base[0] + (size_t)(i + 3) * 4 * CC;
            l1 = base[1] + (size_t)(i + 3) * 4 * CC;
        }
        const bool doSts = (i <= 125);
        step2<4>(sm, src, dst, i % 3, 0, clsA, skpA, s, tid, esum,
                 hold, doSts, (i + 2) % 3, l0, l1, fresh);
        hold[0] = fresh[0]; hold[1] = fresh[1];
    }

    if (tid == 0) {
        // last iter i=127: dst = 0
        #pragma unroll
        for (int q = 0; q < 2; ++q) {
            const float s2 = sm.A[q][0][PAD + SS - 1] + sm.A[q][0][PAD + SS - 2];
            out[2 * c + q] = -(logf(s2) + LN2F * (float)esum[q]);
        }
    }
}

extern "C" void kernel_launch(void* const* d_in, const int* in_sizes, int n_in,
                              void* d_out, int out_size)
{
    const int* yt;
    const float* yp;
    if (in_sizes[0] < in_sizes[1]) {
        yt = (const int*)d_in[0];
        yp = (const float*)d_in[1];
    } else {
        yt = (const int*)d_in[1];
        yp = (const float*)d_in[0];
    }
    ctc_dual<<<128, NTH>>>(yt, yp, (float*)d_out);
}